// round 16
// baseline (speedup 1.0000x reference)
#include <cuda_runtime.h>
#include <cuda_bf16.h>
#include <cstdint>
#include <math.h>

#define EPS 1e-9f
#define BATCH 64
#define HW1 64
#define HW2 28
#define NROUTES 6272
#define NCAPS 10
#define ODIM 16
#define JDIM 8
#define RBLOCKS 392
#define NPER 16
#define NREP 8

typedef unsigned long long u64;
typedef unsigned int u32;

__device__ float g_h[(size_t)BATCH*64*HW1*HW1];
__device__ __nv_bfloat16 g_wbf2[64*2*64*96];         // [ic][split][oc][96]
__device__ float g_u[(size_t)NROUTES*BATCH*JDIM];    // [n][b][8]
__device__ float g_v[BATCH*NCAPS*ODIM];
__device__ float g_sR[NREP*BATCH*NCAPS*ODIM];

__device__ __forceinline__ u64 pack2(float x){u64 r;asm("mov.b64 %0,{%1,%1};":"=l"(r):"f"(x));return r;}
__device__ __forceinline__ u64 packpair(float a,float b){u64 r;asm("mov.b64 %0,{%1,%2};":"=l"(r):"f"(a),"f"(b));return r;}
__device__ __forceinline__ void ffma2(u64&d,u64 a,u64 b){asm("fma.rn.f32x2 %0,%1,%2,%0;":"+l"(d):"l"(a),"l"(b));}
__device__ __forceinline__ float2 unpack2(u64 a){float2 f;asm("mov.b64 {%0,%1},%2;":"=f"(f.x),"=f"(f.y):"l"(a));return f;}
__device__ __forceinline__ void cpasync16(u32 s,const void* g){asm volatile("cp.async.cg.shared.global [%0],[%1],16;"::"r"(s),"l"(g));}
__device__ __forceinline__ void cpcommit(){asm volatile("cp.async.commit_group;");}
__device__ __forceinline__ void cpwait0(){asm volatile("cp.async.wait_group 0;");}

__device__ __forceinline__ void ldsm_x4(u32& r0,u32& r1,u32& r2,u32& r3,u32 a){
    asm volatile("ldmatrix.sync.aligned.m8n8.x4.shared.b16 {%0,%1,%2,%3},[%4];"
        :"=r"(r0),"=r"(r1),"=r"(r2),"=r"(r3):"r"(a));
}
__device__ __forceinline__ void mma_bf16(float* d,const u32* a,u32 b0,u32 b1){
    asm volatile("mma.sync.aligned.m16n8k16.row.col.f32.bf16.bf16.f32 "
        "{%0,%1,%2,%3},{%4,%5,%6,%7},{%8,%9},{%0,%1,%2,%3};"
        :"+f"(d[0]),"+f"(d[1]),"+f"(d[2]),"+f"(d[3])
        :"r"(a[0]),"r"(a[1]),"r"(a[2]),"r"(a[3]),"r"(b0),"r"(b1));
}

// ============================================================
// one-time: conv2 weights -> bf16 hi/lo [ic][split][oc][96]
// split over 2 launches (idx0 = offset) for profiler slotting
__global__ __launch_bounds__(256) void wbf_transform_kernel(const float* __restrict__ w, int idx0)
{
    int idx = idx0 + blockIdx.x*256 + threadIdx.x;
    if (idx >= 64*2*64*96) return;
    int ic = idx / 12288;
    int rem = idx - ic*12288;
    int s = rem / 6144;
    int oc = (rem / 96) & 63;
    int k = rem % 96;
    float val = (k < 81) ? w[(size_t)(oc*64+ic)*81 + k] : 0.f;
    __nv_bfloat16 hi = __float2bfloat16(val);
    g_wbf2[idx] = s ? __float2bfloat16(val - __bfloat162float(hi)) : hi;
}

// ============================================================
// conv1 (unchanged, f32x2); z0 = batch offset for split launch
__global__ __launch_bounds__(256) void conv1_kernel(
    const float* __restrict__ x, const float* __restrict__ w, const float* __restrict__ bias, int z0)
{
    __shared__ float xs[20][20];
    __shared__ u64 ws2[25*32];
    __shared__ float bs[64];
    int b = blockIdx.z + z0, ty0 = blockIdx.y*16, tx0 = blockIdx.x*16;
    int tid = threadIdx.y*16 + threadIdx.x;
    for (int i = tid; i < 25*32; i += 256) {
        int k = i>>5, p = i&31;
        ws2[i] = packpair(w[(2*p)*25+k], w[(2*p+1)*25+k]);
    }
    if (tid < 64) bs[tid] = bias[tid];
    const float* xb = x + (size_t)b*HW1*HW1;
    for (int i = tid; i < 400; i += 256) {
        int r = i/20, c = i%20, gy = ty0+r-2, gx = tx0+c-2;
        float v = 0.f;
        if (gy>=0 && gy<HW1 && gx>=0 && gx<HW1) v = xb[gy*HW1+gx];
        xs[r][c] = v;
    }
    __syncthreads();
    int ty = threadIdx.y, tx = threadIdx.x;
    u64 in2[25];
#pragma unroll
    for (int kh = 0; kh < 5; kh++)
#pragma unroll
        for (int kw = 0; kw < 5; kw++) in2[kh*5+kw] = pack2(xs[ty+kh][tx+kw]);
    float* hout = g_h + ((size_t)b*64)*HW1*HW1 + (ty0+ty)*HW1 + tx0+tx;
#pragma unroll 4
    for (int p = 0; p < 32; p++) {
        u64 acc = packpair(bs[2*p], bs[2*p+1]);
#pragma unroll
        for (int k = 0; k < 25; k++) ffma2(acc, in2[k], ws2[k*32+p]);
        float2 f = unpack2(acc);
        hout[(size_t)(2*p)*HW1*HW1]   = fmaxf(f.x, 0.f);
        hout[(size_t)(2*p+1)*HW1*HW1] = fmaxf(f.y, 0.f);
    }
}

// ============================================================
// conv2 via mma.sync bf16 split-3 (unchanged 889us body);
// t0 = row-tile offset for split launch (profiling slot 6)
#define APITCH 208
#define A_HI 0
#define A_LO 23296
#define B_OFF 46592          // [buf][split][64][208B]
#define INS_OFF 99840        // [buf][15 x 68 floats]
#define INS_PITCH 68
#define TC_SMEM (108000 + 1024)

__global__ __launch_bounds__(256, 2) void conv2_mma_kernel(const float* __restrict__ bias, int t0)
{
    extern __shared__ char smraw[];
    char* sm = (char*)((((size_t)smraw) + 1023) & ~(size_t)1023);
    u32 smb = (u32)__cvta_generic_to_shared(sm);

    int tid = threadIdx.x, w = tid>>5, lane = tid&31;
    int b = blockIdx.y, t = blockIdx.x + t0;

    // zero A hi+lo (k-pad cols 82..95 stay zero forever)
    for (int i = tid; i < 11648; i += 256) ((u32*)sm)[i] = 0;

    const float* insrc = g_h + (size_t)b*64*4096 + (size_t)(8*t)*64;

    auto stageB = [&](int ic, int buf) {
        const __nv_bfloat16* src = g_wbf2 + (size_t)ic*12288;
        u32 dstb = smb + B_OFF + buf*26624;
#pragma unroll
        for (int k = 0; k < 6; k++) {
            int i = tid + k*256;          // 0..1535
            int s = i / 768;
            int r = i - s*768;
            int n = r / 12, c = r - n*12;
            cpasync16(dstb + s*13312 + n*APITCH + c*16, src + (size_t)s*6144 + n*96 + c*8);
        }
    };
    auto stageI = [&](int ic, int buf) {
        if (tid < 240) {
            int r = tid >> 4, c = tid & 15;
            cpasync16(smb + INS_OFF + buf*4080 + r*(INS_PITCH*4) + c*16,
                      insrc + (size_t)ic*4096 + tid*4);
        }
    };

    float acc[8][4];
#pragma unroll
    for (int nt = 0; nt < 8; nt++)
#pragma unroll
        for (int k = 0; k < 4; k++) acc[nt][k] = 0.f;

    stageB(0, 0); stageI(0, 0); cpcommit();

    u32 a_row  = (u32)(w*16 + (lane & 15));
    u32 a_kofs = (u32)((lane >> 4) * 8);
    u32 b_nrow = (u32)((lane & 7) + (lane >> 4)*8);
    u32 b_kofs = (u32)(((lane >> 3) & 1) * 8);

    for (int ic = 0; ic < 64; ic++) {
        int cur = ic & 1;
        cpwait0();
        __syncthreads();                 // staged(cur) ready; prev mma done

        // im2col A hi/lo: warp w owns pixels w*14..w*14+13, lane = j
        {
            const float* insf = (const float*)(sm + INS_OFF + cur*4080);
            int p0 = w*14;
#pragma unroll 2
            for (int pi = 0; pi < 14; pi++) {
                int p = p0 + pi;
                int pr = (p*2341) >> 16;         // p/28
                int inb = pr*(2*INS_PITCH) + 2*(p - pr*28);
#pragma unroll
                for (int half = 0; half < 2; half++) {
                    int j = lane + half*32;
                    if (j > 40) break;
                    int q0 = 2*j, q1 = q0+1;
                    int kh0 = (q0*456)>>12, kw0 = q0 - kh0*9;
                    float v0 = insf[inb + kh0*INS_PITCH + kw0];
                    float v1 = 0.f;
                    if (q1 <= 80) {
                        int kh1 = (q1*456)>>12, kw1 = q1 - kh1*9;
                        v1 = insf[inb + kh1*INS_PITCH + kw1];
                    }
                    __nv_bfloat16 h0 = __float2bfloat16(v0), h1 = __float2bfloat16(v1);
                    __nv_bfloat16 l0 = __float2bfloat16(v0 - __bfloat162float(h0));
                    __nv_bfloat16 l1 = __float2bfloat16(v1 - __bfloat162float(h1));
                    u32 whi = (u32)__bfloat16_as_ushort(h0) | ((u32)__bfloat16_as_ushort(h1)<<16);
                    u32 wlo = (u32)__bfloat16_as_ushort(l0) | ((u32)__bfloat16_as_ushort(l1)<<16);
                    int off = p*APITCH + j*4;
                    *(u32*)(sm + A_HI + off) = whi;
                    *(u32*)(sm + A_LO + off) = wlo;
                }
            }
        }
        if (ic < 63) { stageB(ic+1, cur^1); stageI(ic+1, cur^1); cpcommit(); }
        __syncthreads();                 // A ready

        if (w < 7) {
            u32 bbase = smb + B_OFF + cur*26624;
#pragma unroll
            for (int ks = 0; ks < 6; ks++) {
                u32 k0 = ks*16;
                u32 ah[4], al[4];
                ldsm_x4(ah[0], ah[1], ah[2], ah[3], smb + A_HI + a_row*APITCH + (k0 + a_kofs)*2);
                ldsm_x4(al[0], al[1], al[2], al[3], smb + A_LO + a_row*APITCH + (k0 + a_kofs)*2);
#pragma unroll
                for (int ntp = 0; ntp < 4; ntp++) {
                    u32 brow = (ntp*16 + b_nrow)*APITCH + (k0 + b_kofs)*2;
                    u32 bh[4], bl[4];
                    ldsm_x4(bh[0], bh[1], bh[2], bh[3], bbase + brow);
                    ldsm_x4(bl[0], bl[1], bl[2], bl[3], bbase + 13312 + brow);
                    mma_bf16(acc[2*ntp],   ah, bh[0], bh[1]);
                    mma_bf16(acc[2*ntp+1], ah, bh[2], bh[3]);
                    mma_bf16(acc[2*ntp],   al, bh[0], bh[1]);
                    mma_bf16(acc[2*ntp+1], al, bh[2], bh[3]);
                    mma_bf16(acc[2*ntp],   ah, bl[0], bl[1]);
                    mma_bf16(acc[2*ntp+1], ah, bl[2], bl[3]);
                }
            }
        }
    }

    if (w < 7) {
        int c2 = (lane & 3)*2;
        float b0v[8], b1v[8];
#pragma unroll
        for (int nt = 0; nt < 8; nt++) { b0v[nt] = bias[nt*8 + c2]; b1v[nt] = bias[nt*8 + c2 + 1]; }
#pragma unroll
        for (int rr = 0; rr < 2; rr++) {
            int pp = w*16 + (lane >> 2) + rr*8;
            int n_base = 112*t + pp;
#pragma unroll
            for (int nt = 0; nt < 8; nt++) {
                float a0 = acc[nt][rr*2]   + b0v[nt];
                float a1 = acc[nt][rr*2+1] + b1v[nt];
                float part = a0*a0 + a1*a1;
                part += __shfl_xor_sync(0xffffffff, part, 1);
                part += __shfl_xor_sync(0xffffffff, part, 2);
                float mag = sqrtf(part + EPS);
                float scale = part/(1.f+part)/(mag+EPS);
                float* up = g_u + ((size_t)(nt*784 + n_base)*BATCH + b)*JDIM + c2;
                *(float2*)up = make_float2(a0*scale, a1*scale);
            }
        }
    }
}

// ============================================================
// routing sweep (unchanged from 889us build)
#define R_WS  (NPER*1280)
#define R_USA (NPER*32*4)
#define R_USB (NPER*32*4)
#define R_EX  (2*NCAPS*32)
#define R_SMEM ((R_WS + R_USA + R_USB + R_EX)*4)

__global__ __launch_bounds__(320, 2) void route_kernel(const float* __restrict__ W, int iter)
{
    extern __shared__ float dsm[];
    float* Ws  = dsm;
    float* usA = dsm + R_WS;
    float* usB = dsm + R_WS + R_USA;
    float* ex  = dsm + R_WS + R_USA + R_USB;

    int tid = threadIdx.x, o = tid>>5, lane = tid&31;
    int h = blockIdx.y, bb = h*32 + lane;
    int n0 = blockIdx.x * NPER;

    u32 s_ws  = (u32)__cvta_generic_to_shared(Ws);
    u32 s_usA = (u32)__cvta_generic_to_shared(usA);
    u32 s_usB = (u32)__cvta_generic_to_shared(usB);

    const float* wsrc = W + (size_t)n0*1280;
#pragma unroll
    for (int k = 0; k < 16; k++) {
        int i = tid + k*320;
        cpasync16(s_ws + i*16, wsrc + (size_t)i*4);
    }
#pragma unroll
    for (int k = 0; k < 4; k++) {
        int i = tid + k*320;
        if (i < 1024) {
            int nn = i>>6, rem = i&63, half = rem>>5, ll = rem&31;
            u32 dst = (half ? s_usB : s_usA) + (nn*32 + ll)*16;
            cpasync16(dst, g_u + ((size_t)(n0+nn)*BATCH + h*32 + ll)*JDIM + half*4);
        }
    }
    cpcommit();

    float v[16];
    if (iter > 0) {
        const float4* vp = (const float4*)(g_v + (bb*NCAPS + o)*ODIM);
#pragma unroll
        for (int k = 0; k < 4; k++) {
            float4 f = vp[k];
            v[4*k]=f.x; v[4*k+1]=f.y; v[4*k+2]=f.z; v[4*k+3]=f.w;
        }
    }
    float acc[16];
#pragma unroll
    for (int i = 0; i < 16; i++) acc[i] = 0.f;

    cpwait0();
    __syncthreads();

    for (int nn = 0; nn < NPER; nn++) {
        float4 ua = ((const float4*)usA)[nn*32 + lane];
        float4 ub = ((const float4*)usB)[nn*32 + lane];
        float uh[16];
        const float* wrow = Ws + nn*1280 + o*128;
#pragma unroll
        for (int i = 0; i < 16; i++) {
            float4 wa = *(const float4*)(wrow + i*8);
            float4 wb = *(const float4*)(wrow + i*8 + 4);
            float s = wa.x*ua.x;
            s = fmaf(wa.y,ua.y,s); s = fmaf(wa.z,ua.z,s); s = fmaf(wa.w,ua.w,s);
            s = fmaf(wb.x,ub.x,s); s = fmaf(wb.y,ub.y,s);
            s = fmaf(wb.z,ub.z,s); s = fmaf(wb.w,ub.w,s);
            uh[i] = s;
        }
        float c;
        if (iter == 0) c = 0.1f;
        else {
            float bnew = 0.f;
#pragma unroll
            for (int i = 0; i < 16; i++) bnew = fmaf(uh[i], v[i], bnew);
            float e = __expf(bnew);
            int par = nn & 1;
            ex[(par*NCAPS + o)*32 + lane] = e;
            __syncthreads();
            float denom = 0.f;
#pragma unroll
            for (int k = 0; k < 10; k++) denom += ex[(par*NCAPS + k)*32 + lane];
            c = __fdividef(e, denom);
        }
#pragma unroll
        for (int i = 0; i < 16; i++) acc[i] = fmaf(c, uh[i], acc[i]);
    }
    int rep = (blockIdx.x*2 + blockIdx.y) & (NREP-1);
    float* sp = g_sR + rep*(BATCH*NCAPS*ODIM) + (bb*NCAPS + o)*ODIM;
#pragma unroll
    for (int i = 0; i < 16; i++) atomicAdd(&sp[i], acc[i]);
}

// ============================================================
__global__ __launch_bounds__(256) void squash_v_kernel(float* __restrict__ out, int mode)
{
    int tid = blockIdx.x*256 + threadIdx.x;
    int boq = tid>>2, quad = tid&3;
    float4 s = make_float4(0.f,0.f,0.f,0.f);
#pragma unroll
    for (int r = 0; r < NREP; r++) {
        float* p = g_sR + r*(BATCH*NCAPS*ODIM) + boq*ODIM + quad*4;
        float4 t = *(const float4*)p;
        *(float4*)p = make_float4(0.f,0.f,0.f,0.f);
        s.x += t.x; s.y += t.y; s.z += t.z; s.w += t.w;
    }
    float part = s.x*s.x + s.y*s.y + s.z*s.z + s.w*s.w;
    part += __shfl_xor_sync(0xffffffff, part, 1);
    part += __shfl_xor_sync(0xffffffff, part, 2);
    float msq = part;
    float mag = sqrtf(msq + EPS);
    float scale = msq/(1.f+msq)/(mag+EPS);
    float4 vv = make_float4(s.x*scale, s.y*scale, s.z*scale, s.w*scale);
    if (mode == 0) *(float4*)(g_v + boq*ODIM + quad*4) = vv;
    else if (mode == 1) {
        float4 old = *(const float4*)(g_v + boq*ODIM + quad*4);
        old.x += vv.x; old.y += vv.y; old.z += vv.z; old.w += vv.w;
        *(float4*)(g_v + boq*ODIM + quad*4) = old;
    } else *(float4*)(out + boq*ODIM + quad*4) = vv;
}

// ============================================================
extern "C" void kernel_launch(void* const* d_in, const int* in_sizes, int n_in,
                              void* d_out, int out_size)
{
    const float* x   = (const float*)d_in[0];
    const float* c1w = (const float*)d_in[1];
    const float* c1b = (const float*)d_in[2];
    const float* pw  = (const float*)d_in[3];
    const float* pb  = (const float*)d_in[4];
    const float* W   = (const float*)d_in[5];
    float* out = (float*)d_out;

    static int attr_done = 0;
    if (!attr_done) {
        cudaFuncSetAttribute(conv2_mma_kernel, cudaFuncAttributeMaxDynamicSharedMemorySize, TC_SMEM);
        cudaFuncSetAttribute(route_kernel, cudaFuncAttributeMaxDynamicSharedMemorySize, R_SMEM);
        attr_done = 1;
    }

    // launch order arranged so launch #6 (ncu -s 5 -c 1) = conv2 bulk
    int half = (64*2*64*96)/2;                               // 786432/2
    wbf_transform_kernel<<<half/256, 256>>>(pw, 0);          // 1
    wbf_transform_kernel<<<half/256, 256>>>(pw, half);       // 2
    conv1_kernel<<<dim3(4,4,32), dim3(16,16)>>>(x, c1w, c1b, 0);   // 3
    conv1_kernel<<<dim3(4,4,32), dim3(16,16)>>>(x, c1w, c1b, 32);  // 4
    conv2_mma_kernel<<<dim3(3,64), 256, TC_SMEM>>>(pb, 0);   // 5
    conv2_mma_kernel<<<dim3(4,64), 256, TC_SMEM>>>(pb, 3);   // 6  <- profiled

    route_kernel<<<dim3(RBLOCKS,2), 320, R_SMEM>>>(W, 0);
    squash_v_kernel<<<10, 256>>>(out, 0);
    route_kernel<<<dim3(RBLOCKS,2), 320, R_SMEM>>>(W, 1);
    squash_v_kernel<<<10, 256>>>(out, 1);
    route_kernel<<<dim3(RBLOCKS,2), 320, R_SMEM>>>(W, 2);
    squash_v_kernel<<<10, 256>>>(out, 2);
}